// round 2
// baseline (speedup 1.0000x reference)
#include <cuda_runtime.h>
#include <math.h>

#define B_  8
#define P_  64
#define T_  512
#define D_  256
#define H_  8
#define DK_ 32
#define FF_ 512
#define N_  (B_*T_*P_)   // 262144 rows

// ---------------- scratch (static device globals; no allocations) ----------
__device__ float g_qkv[201326592];   // N*768 (reused for FF1 out N*512)
__device__ float g_xn [67108864];    // N*256 (LN1 out; reused for attn out)
__device__ float g_xt2[67108864];    // N*256 (residual-1 result)
__device__ float g_y  [67108864];    // N*256 (LN2 out)
__device__ float g_rel[262144];      // B*H*P*P

// ---------------- relpos: (B,P,2) -> rel_h (B,H,P,P) ------------------------
__global__ void relpos_kernel(const float* __restrict__ pos,
                              const float* __restrict__ w_rel,
                              float* __restrict__ rel)
{
    int bp = blockIdx.x;          // B*P blocks
    int b = bp >> 6, p = bp & 63;
    int q = threadIdx.x;          // 64 threads
    const float DEG = 0.017453292519943295f;
    float latp = pos[(b*64+p)*2]   * DEG;
    float lonp = pos[(b*64+p)*2+1] * DEG;
    float latq = pos[(b*64+q)*2]   * DEG;
    float lonq = pos[(b*64+q)*2+1] * DEG;
    float dlat = latp - latq, dlon = lonp - lonq;
    float dx = dlon * cosf((latp + latq) * 0.5f);
    float dy = dlat;
    float sdl = sinf(dlat*0.5f), sdo = sinf(dlon*0.5f);
    float a = sdl*sdl + cosf(latp)*cosf(latq)*sdo*sdo;
    float sa = fminf(sqrtf(fmaxf(a, 1e-12f)), 1.0f - 1e-7f);
    float dist = 2.0f * 6371.0f * asinf(sa) * (1.0f/500.0f);
    float bearing = atan2f(sinf(dlon)*cosf(latq),
                           cosf(latp)*sinf(latq) - sinf(latp)*cosf(latq)*cosf(dlon));
    float sb = sinf(bearing);
    #pragma unroll
    for (int h = 0; h < 8; h++) {
        float v = dx*w_rel[h] + dy*w_rel[8+h] + dist*w_rel[16+h] + sb*w_rel[24+h];
        rel[(((long)(b*8 + h))*64 + p)*64 + q] = v;
    }
}

// ---------------- LayerNorm (one warp per 256-elem row) ---------------------
// transpose_in=1: read x laid out (B,P,T,D) at logical row (b,t,p)
__global__ void __launch_bounds__(256) ln_kernel(const float* __restrict__ in,
                          const float* __restrict__ g,
                          const float* __restrict__ be,
                          float* __restrict__ out, int transpose_in)
{
    int warp = threadIdx.x >> 5, lane = threadIdx.x & 31;
    long r = (long)blockIdx.x * 8 + warp;
    long src;
    if (transpose_in) {
        int b = (int)(r >> 15), t = (int)(r >> 6) & (T_-1), p = (int)r & (P_-1);
        src = (((long)(b*P_ + p))*T_ + t) * D_;
    } else {
        src = r * D_;
    }
    const float4* in4 = (const float4*)(in + src);
    float4 v0 = in4[lane];
    float4 v1 = in4[lane + 32];
    float s  = v0.x+v0.y+v0.z+v0.w + v1.x+v1.y+v1.z+v1.w;
    float sq = v0.x*v0.x+v0.y*v0.y+v0.z*v0.z+v0.w*v0.w
             + v1.x*v1.x+v1.y*v1.y+v1.z*v1.z+v1.w*v1.w;
    #pragma unroll
    for (int o = 16; o; o >>= 1) {
        s  += __shfl_xor_sync(0xffffffffu, s,  o);
        sq += __shfl_xor_sync(0xffffffffu, sq, o);
    }
    float mean = s * (1.0f/256.0f);
    float var  = sq * (1.0f/256.0f) - mean*mean;
    float rstd = rsqrtf(var + 1e-5f);
    const float4* g4  = (const float4*)g;
    const float4* be4 = (const float4*)be;
    float4 ga = g4[lane],  gb = g4[lane+32];
    float4 ba = be4[lane], bb = be4[lane+32];
    float4 o0, o1;
    o0.x = (v0.x-mean)*rstd*ga.x + ba.x;  o0.y = (v0.y-mean)*rstd*ga.y + ba.y;
    o0.z = (v0.z-mean)*rstd*ga.z + ba.z;  o0.w = (v0.w-mean)*rstd*ga.w + ba.w;
    o1.x = (v1.x-mean)*rstd*gb.x + bb.x;  o1.y = (v1.y-mean)*rstd*gb.y + bb.y;
    o1.z = (v1.z-mean)*rstd*gb.z + bb.z;  o1.w = (v1.w-mean)*rstd*gb.w + bb.w;
    float4* o4 = (float4*)(out + r * D_);
    o4[lane]      = o0;
    o4[lane + 32] = o1;
}

// ---------------- attention: one block per (b,t,h) --------------------------
__global__ void __launch_bounds__(128) attn_kernel(const float* __restrict__ qkv,
                            const float* __restrict__ rel,
                            float* __restrict__ o)
{
    int blk = blockIdx.x;                  // ((b*T + t)*H + h)
    int h = blk & 7;
    int bt = blk >> 3;
    int t = bt & (T_-1);
    int b = bt >> 9;

    __shared__ float qs[64][36];
    __shared__ float ks[64][36];
    __shared__ float vs[64][36];
    __shared__ float ss[64][65];

    const float* base = qkv + ((long)(b*T_ + t)) * P_ * 768;
    int tid = threadIdx.x;
    for (int i = tid; i < 64*32; i += 128) {
        int p = i >> 5, d = i & 31;
        qs[p][d] = base[p*768 +        h*32 + d];
        ks[p][d] = base[p*768 + 256  + h*32 + d];
        vs[p][d] = base[p*768 + 512  + h*32 + d];
    }
    __syncthreads();

    const float scale = 0.17677669529663687f;  // 1/sqrt(32)
    const float* relb = rel + ((long)(b*8 + h)) * 64 * 64;

    int p  = tid >> 1;
    int q0 = (tid & 1) * 32;

    // hoist q row into registers
    float qreg[32];
    #pragma unroll
    for (int j = 0; j < 8; j++) {
        float4 t4 = *(const float4*)&qs[p][j*4];
        qreg[j*4+0]=t4.x; qreg[j*4+1]=t4.y; qreg[j*4+2]=t4.z; qreg[j*4+3]=t4.w;
    }
    for (int qq = q0; qq < q0 + 32; qq++) {
        float s = 0.0f;
        #pragma unroll
        for (int j = 0; j < 8; j++) {
            float4 k4 = *(const float4*)&ks[qq][j*4];
            s += qreg[j*4+0]*k4.x + qreg[j*4+1]*k4.y + qreg[j*4+2]*k4.z + qreg[j*4+3]*k4.w;
        }
        ss[p][qq] = s * scale + relb[p*64 + qq];
    }
    __syncthreads();

    // softmax: 2 threads per row (half = 32 elems), combine via shfl
    {
        int row = tid >> 1, half = tid & 1;
        float m = -1e30f;
        #pragma unroll
        for (int i = 0; i < 32; i++) m = fmaxf(m, ss[row][half*32 + i]);
        m = fmaxf(m, __shfl_xor_sync(0xffffffffu, m, 1));
        float sum = 0.0f;
        #pragma unroll
        for (int i = 0; i < 32; i++) {
            float e = __expf(ss[row][half*32 + i] - m);
            ss[row][half*32 + i] = e;
            sum += e;
        }
        sum += __shfl_xor_sync(0xffffffffu, sum, 1);
        float inv = 1.0f / sum;
        #pragma unroll
        for (int i = 0; i < 32; i++) ss[row][half*32 + i] *= inv;
    }
    __syncthreads();

    // PV: each thread -> row p, 16 d's
    int d0 = (tid & 1) * 16;
    float acc[16];
    #pragma unroll
    for (int i = 0; i < 16; i++) acc[i] = 0.0f;
    for (int qq = 0; qq < 64; qq++) {
        float sv = ss[p][qq];
        #pragma unroll
        for (int j = 0; j < 4; j++) {
            float4 v4 = *(const float4*)&vs[qq][d0 + j*4];
            acc[j*4+0] += sv*v4.x; acc[j*4+1] += sv*v4.y;
            acc[j*4+2] += sv*v4.z; acc[j*4+3] += sv*v4.w;
        }
    }
    float* ob = o + ((long)(b*T_ + t)) * P_ * 256;   // (B,T,P,D)
    #pragma unroll
    for (int j = 0; j < 4; j++) {
        float4 v; v.x=acc[j*4+0]; v.y=acc[j*4+1]; v.z=acc[j*4+2]; v.w=acc[j*4+3];
        *(float4*)&ob[p*256 + h*32 + d0 + j*4] = v;
    }
}

// ---------------- generic 128x128x8 SGEMM with fused epilogues --------------
// MODE 0: C = A@W + bias
// MODE 1: C = A@W + bias + x_transposed_residual           (out-proj, M=256)
// MODE 2: C = gelu(A@W + bias)                             (FF1)
// MODE 3: out_transposed = A@W + bias + y_residual         (FF2, M=256)
__device__ __forceinline__ float gelu_exact(float x) { return x * normcdff(x); }

template<int MODE>
__global__ void __launch_bounds__(256) gemm_ep(const float* __restrict__ A,
                        const float* __restrict__ W,
                        const float* __restrict__ bias,
                        float* __restrict__ C,
                        int K, int M,
                        const float* __restrict__ aux)
{
    __shared__ float As[8][128];
    __shared__ float Bs[8][128];
    int tid = threadIdx.x;
    int tx = tid & 15, ty = tid >> 4;
    long r0 = (long)blockIdx.y * 128;
    int  c0 = blockIdx.x * 128;

    int arow = tid >> 1,  akq  = (tid & 1) * 4;
    int brow = tid >> 5,  bcol = (tid & 31) * 4;

    float acc[8][8];
    #pragma unroll
    for (int i = 0; i < 8; i++)
        #pragma unroll
        for (int j = 0; j < 8; j++) acc[i][j] = 0.0f;

    for (int kt = 0; kt < K; kt += 8) {
        __syncthreads();
        float4 av = *(const float4*)(A + (r0 + arow)*K + kt + akq);
        As[akq+0][arow] = av.x;
        As[akq+1][arow] = av.y;
        As[akq+2][arow] = av.z;
        As[akq+3][arow] = av.w;
        *(float4*)&Bs[brow][bcol] = *(const float4*)(W + (long)(kt + brow)*M + c0 + bcol);
        __syncthreads();
        #pragma unroll
        for (int k = 0; k < 8; k++) {
            float4 a0 = *(float4*)&As[k][ty*4];
            float4 a1 = *(float4*)&As[k][ty*4 + 64];
            float4 b0 = *(float4*)&Bs[k][tx*4];
            float4 b1 = *(float4*)&Bs[k][tx*4 + 64];
            float ar[8] = {a0.x,a0.y,a0.z,a0.w,a1.x,a1.y,a1.z,a1.w};
            float br[8] = {b0.x,b0.y,b0.z,b0.w,b1.x,b1.y,b1.z,b1.w};
            #pragma unroll
            for (int i = 0; i < 8; i++)
                #pragma unroll
                for (int j = 0; j < 8; j++)
                    acc[i][j] += ar[i]*br[j];
        }
    }

    #pragma unroll
    for (int ii = 0; ii < 2; ii++)
    #pragma unroll
    for (int i = 0; i < 4; i++) {
        long row = r0 + ii*64 + ty*4 + i;
        long trow = 0;
        if (MODE == 1 || MODE == 3) {
            int b = (int)(row >> 15), t = (int)(row >> 6) & (T_-1), p = (int)row & (P_-1);
            trow = (((long)(b*P_ + p))*T_ + t) * D_;
        }
        #pragma unroll
        for (int jj = 0; jj < 2; jj++) {
            int col = c0 + jj*64 + tx*4;
            float4 v;
            v.x = acc[ii*4+i][jj*4+0];
            v.y = acc[ii*4+i][jj*4+1];
            v.z = acc[ii*4+i][jj*4+2];
            v.w = acc[ii*4+i][jj*4+3];
            float4 bb = *(const float4*)(bias + col);
            v.x += bb.x; v.y += bb.y; v.z += bb.z; v.w += bb.w;
            if (MODE == 0) {
                *(float4*)(C + row*M + col) = v;
            } else if (MODE == 1) {
                float4 xr = *(const float4*)(aux + trow + col);
                v.x += xr.x; v.y += xr.y; v.z += xr.z; v.w += xr.w;
                *(float4*)(C + row*D_ + col) = v;
            } else if (MODE == 2) {
                v.x = gelu_exact(v.x); v.y = gelu_exact(v.y);
                v.z = gelu_exact(v.z); v.w = gelu_exact(v.w);
                *(float4*)(C + row*M + col) = v;
            } else {
                float4 yr = *(const float4*)(aux + row*D_ + col);
                v.x += yr.x; v.y += yr.y; v.z += yr.z; v.w += yr.w;
                *(float4*)(C + trow + col) = v;
            }
        }
    }
}

// ---------------- launch --------------------------------------------------
extern "C" void kernel_launch(void* const* d_in, const int* in_sizes, int n_in,
                              void* d_out, int out_size)
{
    const float* x     = (const float*)d_in[0];
    const float* pos   = (const float*)d_in[1];
    const float* w_qkv = (const float*)d_in[2];
    const float* b_qkv = (const float*)d_in[3];
    const float* w_out = (const float*)d_in[4];
    const float* b_out = (const float*)d_in[5];
    const float* w_ff1 = (const float*)d_in[6];
    const float* b_ff1 = (const float*)d_in[7];
    const float* w_ff2 = (const float*)d_in[8];
    const float* b_ff2 = (const float*)d_in[9];
    const float* w_rel = (const float*)d_in[10];
    const float* g1    = (const float*)d_in[11];
    const float* be1   = (const float*)d_in[12];
    const float* g2    = (const float*)d_in[13];
    const float* be2   = (const float*)d_in[14];
    float* out = (float*)d_out;

    float *qkv, *xn, *xt2, *y, *rel;
    cudaGetSymbolAddress((void**)&qkv, g_qkv);
    cudaGetSymbolAddress((void**)&xn,  g_xn);
    cudaGetSymbolAddress((void**)&xt2, g_xt2);
    cudaGetSymbolAddress((void**)&y,   g_y);
    cudaGetSymbolAddress((void**)&rel, g_rel);

    // 1. relative positional bias
    relpos_kernel<<<B_*P_, 64>>>(pos, w_rel, rel);
    // 2. LN1 + transpose -> xn (B,T,P,D)
    ln_kernel<<<N_/8, 256>>>(x, g1, be1, xn, 1);
    // 3. QKV projection: (N,256)@(256,768)
    gemm_ep<0><<<dim3(768/128, N_/128), 256>>>(xn, w_qkv, b_qkv, qkv, 256, 768, nullptr);
    // 4. attention per (b,t,h) -> o into xn buffer (B,T,P,D)
    attn_kernel<<<B_*T_*H_, 128>>>(qkv, rel, xn);
    // 5. out projection + transposed residual(x) -> xt2
    gemm_ep<1><<<dim3(256/128, N_/128), 256>>>(xn, w_out, b_out, xt2, 256, 256, x);
    // 6. LN2 -> y
    ln_kernel<<<N_/8, 256>>>(xt2, g2, be2, y, 0);
    // 7. FF1 + GELU -> reuse qkv buffer
    gemm_ep<2><<<dim3(512/128, N_/128), 256>>>(y, w_ff1, b_ff1, qkv, 256, 512, nullptr);
    // 8. FF2 + residual(y) -> transposed store into d_out (B,P,T,D)
    gemm_ep<3><<<dim3(256/128, N_/128), 256>>>(qkv, w_ff2, b_ff2, out, 512, 256, y);
}

// round 4
// speedup vs baseline: 1.7011x; 1.7011x over previous
#include <cuda_runtime.h>
#include <cuda_bf16.h>
#include <cstdint>
#include <math.h>

#define B_  8
#define P_  64
#define T_  512
#define D_  256
#define H_  8
#define FF_ 512
#define N_  (B_*T_*P_)   // 262144 rows

// ---------------- scratch (static device globals; no allocations) ----------
__device__ float g_qkv[201326592];                 // N*768 fp32
__device__ float g_xt2[67108864];                  // N*256 fp32
__device__ float g_y  [67108864];                  // N*256 fp32
__device__ float g_rel[262144];                    // B*H*P*P
__device__ __nv_bfloat16 g_act_h[67108864], g_act_l[67108864];    // N*256 (reused)
__device__ __nv_bfloat16 g_gel_h[134217728], g_gel_l[134217728];  // N*512
__device__ __nv_bfloat16 g_wqkv_h[196608], g_wqkv_l[196608];      // [768,256]
__device__ __nv_bfloat16 g_wout_h[65536],  g_wout_l[65536];       // [256,256]
__device__ __nv_bfloat16 g_wff1_h[131072], g_wff1_l[131072];      // [512,256]
__device__ __nv_bfloat16 g_wff2_h[131072], g_wff2_l[131072];      // [256,512]

// ---------------- helpers ----------------------------------------------
__device__ __forceinline__ uint32_t smem_u32(const void* p) {
    uint32_t a;
    asm("{ .reg .u64 t; cvta.to.shared.u64 t, %1; cvt.u32.u64 %0, t; }" : "=r"(a) : "l"(p));
    return a;
}
#define SW128(o) ((o) ^ (((o) >> 3) & 0x70))

__device__ __forceinline__ void cpasync16(uint32_t s, const void* g) {
    asm volatile("cp.async.cg.shared.global [%0], [%1], 16;" :: "r"(s), "l"(g));
}
#define CP_COMMIT() asm volatile("cp.async.commit_group;" ::: "memory")
#define CP_WAIT(n)  asm volatile("cp.async.wait_group %0;" :: "n"(n) : "memory")

__device__ __forceinline__ void ldsm4(uint32_t* r, uint32_t addr) {
    asm volatile("ldmatrix.sync.aligned.m8n8.x4.shared.b16 {%0,%1,%2,%3}, [%4];"
        : "=r"(r[0]), "=r"(r[1]), "=r"(r[2]), "=r"(r[3]) : "r"(addr));
}
__device__ __forceinline__ void mma16816(float* d, const uint32_t* a, const uint32_t* b) {
    asm volatile("mma.sync.aligned.m16n8k16.row.col.f32.bf16.bf16.f32 "
        "{%0,%1,%2,%3}, {%4,%5,%6,%7}, {%8,%9}, {%0,%1,%2,%3};"
        : "+f"(d[0]), "+f"(d[1]), "+f"(d[2]), "+f"(d[3])
        : "r"(a[0]), "r"(a[1]), "r"(a[2]), "r"(a[3]), "r"(b[0]), "r"(b[1]));
}

struct alignas(8) bf16x4 { __nv_bfloat16 a, b, c, d; };
__device__ __forceinline__ void split1(float v, __nv_bfloat16& h, __nv_bfloat16& l) {
    h = __float2bfloat16(v);
    l = __float2bfloat16(v - __bfloat162float(h));
}
__device__ __forceinline__ void store_split4(__nv_bfloat16* ph, __nv_bfloat16* pl, float4 v) {
    bf16x4 H, L;
    split1(v.x, H.a, L.a); split1(v.y, H.b, L.b);
    split1(v.z, H.c, L.c); split1(v.w, H.d, L.d);
    *(bf16x4*)ph = H;
    *(bf16x4*)pl = L;
}
__device__ __forceinline__ void store_split2(__nv_bfloat16* ph, __nv_bfloat16* pl, float2 v) {
    __nv_bfloat16 h0, l0, h1, l1;
    split1(v.x, h0, l0); split1(v.y, h1, l1);
    uint32_t hp = (uint32_t)__bfloat16_as_ushort(h0) | ((uint32_t)__bfloat16_as_ushort(h1) << 16);
    uint32_t lp = (uint32_t)__bfloat16_as_ushort(l0) | ((uint32_t)__bfloat16_as_ushort(l1) << 16);
    *(uint32_t*)ph = hp;
    *(uint32_t*)pl = lp;
}

// ---------------- weight convert+transpose: [K,M] f32 -> [M,K] bf16 hi/lo ---
__global__ void wconv_kernel(const float* __restrict__ w,
                             __nv_bfloat16* __restrict__ th,
                             __nv_bfloat16* __restrict__ tl, int K, int M)
{
    int idx = blockIdx.x * 256 + threadIdx.x;
    if (idx >= M * K) return;
    int m = idx / K, k = idx - m * K;
    float v = w[(long)k * M + m];
    __nv_bfloat16 h, l;
    split1(v, h, l);
    th[idx] = h; tl[idx] = l;
}

// ---------------- relpos: (B,P,2) -> rel_h (B,H,P,P) ------------------------
__global__ void relpos_kernel(const float* __restrict__ pos,
                              const float* __restrict__ w_rel,
                              float* __restrict__ rel)
{
    int bp = blockIdx.x;
    int b = bp >> 6, p = bp & 63;
    int q = threadIdx.x;
    const float DEG = 0.017453292519943295f;
    float latp = pos[(b*64+p)*2]   * DEG;
    float lonp = pos[(b*64+p)*2+1] * DEG;
    float latq = pos[(b*64+q)*2]   * DEG;
    float lonq = pos[(b*64+q)*2+1] * DEG;
    float dlat = latp - latq, dlon = lonp - lonq;
    float dx = dlon * cosf((latp + latq) * 0.5f);
    float dy = dlat;
    float sdl = sinf(dlat*0.5f), sdo = sinf(dlon*0.5f);
    float a = sdl*sdl + cosf(latp)*cosf(latq)*sdo*sdo;
    float sa = fminf(sqrtf(fmaxf(a, 1e-12f)), 1.0f - 1e-7f);
    float dist = 2.0f * 6371.0f * asinf(sa) * (1.0f/500.0f);
    float bearing = atan2f(sinf(dlon)*cosf(latq),
                           cosf(latp)*sinf(latq) - sinf(latp)*cosf(latq)*cosf(dlon));
    float sb = sinf(bearing);
    #pragma unroll
    for (int h = 0; h < 8; h++) {
        float v = dx*w_rel[h] + dy*w_rel[8+h] + dist*w_rel[16+h] + sb*w_rel[24+h];
        rel[(((long)(b*8 + h))*64 + p)*64 + q] = v;
    }
}

// ---------------- LayerNorm -> bf16 hi/lo (+ optional f32) ------------------
__global__ void __launch_bounds__(256) ln_kernel(const float* __restrict__ in,
                          const float* __restrict__ g,
                          const float* __restrict__ be,
                          __nv_bfloat16* __restrict__ oh,
                          __nv_bfloat16* __restrict__ ol,
                          float* __restrict__ of32, int transpose_in)
{
    int warp = threadIdx.x >> 5, lane = threadIdx.x & 31;
    long r = (long)blockIdx.x * 8 + warp;
    long src;
    if (transpose_in) {
        int b = (int)(r >> 15), t = (int)(r >> 6) & (T_-1), p = (int)r & (P_-1);
        src = (((long)(b*P_ + p))*T_ + t) * D_;
    } else {
        src = r * D_;
    }
    const float4* in4 = (const float4*)(in + src);
    float4 v0 = in4[lane];
    float4 v1 = in4[lane + 32];
    float s  = v0.x+v0.y+v0.z+v0.w + v1.x+v1.y+v1.z+v1.w;
    float sq = v0.x*v0.x+v0.y*v0.y+v0.z*v0.z+v0.w*v0.w
             + v1.x*v1.x+v1.y*v1.y+v1.z*v1.z+v1.w*v1.w;
    #pragma unroll
    for (int o = 16; o; o >>= 1) {
        s  += __shfl_xor_sync(0xffffffffu, s,  o);
        sq += __shfl_xor_sync(0xffffffffu, sq, o);
    }
    float mean = s * (1.0f/256.0f);
    float var  = sq * (1.0f/256.0f) - mean*mean;
    float rstd = rsqrtf(var + 1e-5f);
    const float4* g4  = (const float4*)g;
    const float4* be4 = (const float4*)be;
    float4 ga = g4[lane],  gb = g4[lane+32];
    float4 ba = be4[lane], bb = be4[lane+32];
    float4 o0, o1;
    o0.x = (v0.x-mean)*rstd*ga.x + ba.x;  o0.y = (v0.y-mean)*rstd*ga.y + ba.y;
    o0.z = (v0.z-mean)*rstd*ga.z + ba.z;  o0.w = (v0.w-mean)*rstd*ga.w + ba.w;
    o1.x = (v1.x-mean)*rstd*gb.x + bb.x;  o1.y = (v1.y-mean)*rstd*gb.y + bb.y;
    o1.z = (v1.z-mean)*rstd*gb.z + bb.z;  o1.w = (v1.w-mean)*rstd*gb.w + bb.w;
    store_split4(oh + r*D_ + lane*4,       ol + r*D_ + lane*4,       o0);
    store_split4(oh + r*D_ + 128 + lane*4, ol + r*D_ + 128 + lane*4, o1);
    if (of32) {
        float4* o4 = (float4*)(of32 + r * D_);
        o4[lane]      = o0;
        o4[lane + 32] = o1;
    }
}

// ---------------- attention: one block per (b,t,h); writes bf16 hi/lo -------
__global__ void __launch_bounds__(128) attn_kernel(const float* __restrict__ qkv,
                            const float* __restrict__ rel,
                            __nv_bfloat16* __restrict__ oh,
                            __nv_bfloat16* __restrict__ ol)
{
    int blk = blockIdx.x;
    int h = blk & 7;
    int bt = blk >> 3;
    int t = bt & (T_-1);
    int b = bt >> 9;

    __shared__ float qs[64][36];
    __shared__ float ks[64][36];
    __shared__ float vs[64][36];
    __shared__ float ss[64][65];

    const float* base = qkv + ((long)(b*T_ + t)) * P_ * 768;
    int tid = threadIdx.x;
    for (int i = tid; i < 64*32; i += 128) {
        int p = i >> 5, d = i & 31;
        qs[p][d] = base[p*768 +        h*32 + d];
        ks[p][d] = base[p*768 + 256  + h*32 + d];
        vs[p][d] = base[p*768 + 512  + h*32 + d];
    }
    __syncthreads();

    const float scale = 0.17677669529663687f;
    const float* relb = rel + ((long)(b*8 + h)) * 64 * 64;

    int p  = tid >> 1;
    int q0 = (tid & 1) * 32;

    float qreg[32];
    #pragma unroll
    for (int j = 0; j < 8; j++) {
        float4 t4 = *(const float4*)&qs[p][j*4];
        qreg[j*4+0]=t4.x; qreg[j*4+1]=t4.y; qreg[j*4+2]=t4.z; qreg[j*4+3]=t4.w;
    }
    for (int qq = q0; qq < q0 + 32; qq++) {
        float s = 0.0f;
        #pragma unroll
        for (int j = 0; j < 8; j++) {
            float4 k4 = *(const float4*)&ks[qq][j*4];
            s += qreg[j*4+0]*k4.x + qreg[j*4+1]*k4.y + qreg[j*4+2]*k4.z + qreg[j*4+3]*k4.w;
        }
        ss[p][qq] = s * scale + relb[p*64 + qq];
    }
    __syncthreads();

    {
        int row = tid >> 1, half = tid & 1;
        float m = -1e30f;
        #pragma unroll
        for (int i = 0; i < 32; i++) m = fmaxf(m, ss[row][half*32 + i]);
        m = fmaxf(m, __shfl_xor_sync(0xffffffffu, m, 1));
        float sum = 0.0f;
        #pragma unroll
        for (int i = 0; i < 32; i++) {
            float e = __expf(ss[row][half*32 + i] - m);
            ss[row][half*32 + i] = e;
            sum += e;
        }
        sum += __shfl_xor_sync(0xffffffffu, sum, 1);
        float inv = 1.0f / sum;
        #pragma unroll
        for (int i = 0; i < 32; i++) ss[row][half*32 + i] *= inv;
    }
    __syncthreads();

    int d0 = (tid & 1) * 16;
    float acc[16];
    #pragma unroll
    for (int i = 0; i < 16; i++) acc[i] = 0.0f;
    for (int qq = 0; qq < 64; qq++) {
        float sv = ss[p][qq];
        #pragma unroll
        for (int j = 0; j < 4; j++) {
            float4 v4 = *(const float4*)&vs[qq][d0 + j*4];
            acc[j*4+0] += sv*v4.x; acc[j*4+1] += sv*v4.y;
            acc[j*4+2] += sv*v4.z; acc[j*4+3] += sv*v4.w;
        }
    }
    long ob = ((long)(b*T_ + t)) * P_ * 256 + p*256 + h*32 + d0;
    #pragma unroll
    for (int j = 0; j < 4; j++) {
        float4 v; v.x=acc[j*4+0]; v.y=acc[j*4+1]; v.z=acc[j*4+2]; v.w=acc[j*4+3];
        store_split4(oh + ob + j*4, ol + ob + j*4, v);
    }
}

// ---------------- HMMA split-bf16 GEMM, 128x128 tile, fused epilogues -------
// MODE 0: Cf = A@W + bias                      (QKV, Mout=768)
// MODE 1: Cf = A@W + bias + x_transposed(aux)  (out-proj, Mout=256)
// MODE 2: Ch/Cl = split(gelu(A@W + bias))      (FF1, Mout=512)
// MODE 3: Cf[transposed] = A@W + bias + aux    (FF2, Mout=256)
// SMEM per buffer: A_h 16K | A_l 16K | B_h 16K | B_l 16K  (K-chunk 64, SW128)
#define GEMM_SMEM (2 * 65536)

template<int MODE>
__global__ void __launch_bounds__(256) gemm_tc(
    const __nv_bfloat16* __restrict__ Ah, const __nv_bfloat16* __restrict__ Al,
    const __nv_bfloat16* __restrict__ Wh, const __nv_bfloat16* __restrict__ Wl,
    const float* __restrict__ bias,
    float* __restrict__ Cf,
    __nv_bfloat16* __restrict__ Ch, __nv_bfloat16* __restrict__ Cl,
    const float* __restrict__ aux,
    int K, int Mout)
{
    extern __shared__ char smem[];
    uint32_t sb = smem_u32(smem);
    int tid = threadIdx.x, wid = tid >> 5, lane = tid & 31;
    long r0 = (long)blockIdx.y * 128;
    int  c0 = blockIdx.x * 128;
    int wm = wid & 3, wn = wid >> 2;

    int NC = K >> 6;

    // ---- prefetch chunk 0 ----
    {
        uint32_t base = sb;
        #pragma unroll
        for (int it = 0; it < 4; it++) {
            int i = tid + it*256;
            int row = i >> 3, kq = i & 7;
            uint32_t sw = SW128((uint32_t)(row*128 + kq*16));
            const __nv_bfloat16* ga = Ah + (r0+row)*(long)K + kq*8;
            const __nv_bfloat16* gl = Al + (r0+row)*(long)K + kq*8;
            const __nv_bfloat16* gwh = Wh + (long)(c0+row)*K + kq*8;
            const __nv_bfloat16* gwl = Wl + (long)(c0+row)*K + kq*8;
            cpasync16(base + sw,          ga);
            cpasync16(base + 16384 + sw,  gl);
            cpasync16(base + 32768 + sw,  gwh);
            cpasync16(base + 49152 + sw,  gwl);
        }
        CP_COMMIT();
    }

    float acc[2][8][4];
    #pragma unroll
    for (int mt = 0; mt < 2; mt++)
        #pragma unroll
        for (int nt = 0; nt < 8; nt++)
            #pragma unroll
            for (int i = 0; i < 4; i++) acc[mt][nt][i] = 0.0f;

    for (int c = 0; c < NC; c++) {
        if (c + 1 < NC) {
            uint32_t base = sb + ((c+1) & 1) * 65536u;
            int kt = (c+1) << 6;
            #pragma unroll
            for (int it = 0; it < 4; it++) {
                int i = tid + it*256;
                int row = i >> 3, kq = i & 7;
                uint32_t sw = SW128((uint32_t)(row*128 + kq*16));
                cpasync16(base + sw,          Ah + (r0+row)*(long)K + kt + kq*8);
                cpasync16(base + 16384 + sw,  Al + (r0+row)*(long)K + kt + kq*8);
                cpasync16(base + 32768 + sw,  Wh + (long)(c0+row)*K + kt + kq*8);
                cpasync16(base + 49152 + sw,  Wl + (long)(c0+row)*K + kt + kq*8);
            }
            CP_COMMIT();
            CP_WAIT(1);
        } else {
            CP_WAIT(0);
        }
        __syncthreads();

        uint32_t base = sb + (c & 1) * 65536u;
        #pragma unroll
        for (int k16 = 0; k16 < 4; k16++) {
            uint32_t ah[2][4], al[2][4], bh[8][2], bl[8][2];
            // A fragments: lanes 0-15 -> rows m0+0..15 @kb, lanes 16-31 -> same rows @kb+16
            #pragma unroll
            for (int mt = 0; mt < 2; mt++) {
                int arow = wm*32 + mt*16 + (lane & 15);
                uint32_t kb = k16*32 + ((lane >> 4) << 4);
                uint32_t off = SW128((uint32_t)(arow*128) + kb);
                ldsm4(ah[mt], base + off);
                ldsm4(al[mt], base + 16384 + off);
            }
            // B fragments: 2 n-tiles per ldsm.x4
            #pragma unroll
            for (int np = 0; np < 4; np++) {
                int brow = wn*64 + np*16 + (lane & 7) + ((lane >> 4) & 1) * 8;
                uint32_t kb = k16*32 + ((lane >> 3) & 1) * 16;
                uint32_t off = SW128((uint32_t)(brow*128) + kb);
                ldsm4(&bh[np*2][0], base + 32768 + off);
                ldsm4(&bl[np*2][0], base + 49152 + off);
            }
            #pragma unroll
            for (int mt = 0; mt < 2; mt++)
                #pragma unroll
                for (int nt = 0; nt < 8; nt++) {
                    mma16816(acc[mt][nt], ah[mt], bh[nt]);
                    mma16816(acc[mt][nt], ah[mt], bl[nt]);
                    mma16816(acc[mt][nt], al[mt], bh[nt]);
                }
        }
        __syncthreads();
    }

    // ---- epilogue ----
    int rowb = wm*32 + (lane >> 2);
    int colb = c0 + wn*64 + (lane & 3) * 2;
    #pragma unroll
    for (int mt = 0; mt < 2; mt++) {
        #pragma unroll
        for (int half = 0; half < 2; half++) {
            long row = r0 + rowb + mt*16 + half*8;
            long trow = 0;
            if (MODE == 1 || MODE == 3) {
                int b = (int)(row >> 15), t = (int)(row >> 6) & (T_-1), p = (int)row & (P_-1);
                trow = (((long)(b*P_ + p))*T_ + t) * D_;
            }
            #pragma unroll
            for (int nt = 0; nt < 8; nt++) {
                int col = colb + nt*8;
                float2 v;
                v.x = acc[mt][nt][half*2+0];
                v.y = acc[mt][nt][half*2+1];
                float2 bb = *(const float2*)(bias + col);
                v.x += bb.x; v.y += bb.y;
                if (MODE == 0) {
                    *(float2*)(Cf + row*(long)Mout + col) = v;
                } else if (MODE == 1) {
                    float2 xr = *(const float2*)(aux + trow + col);
                    v.x += xr.x; v.y += xr.y;
                    *(float2*)(Cf + row*(long)D_ + col) = v;
                } else if (MODE == 2) {
                    v.x = v.x * normcdff(v.x);
                    v.y = v.y * normcdff(v.y);
                    store_split2(Ch + row*(long)Mout + col, Cl + row*(long)Mout + col, v);
                } else {
                    float2 yr = *(const float2*)(aux + row*(long)D_ + col);
                    v.x += yr.x; v.y += yr.y;
                    *(float2*)(Cf + trow + col) = v;
                }
            }
        }
    }
}

// ---------------- launch -----------------------------------------------------
extern "C" void kernel_launch(void* const* d_in, const int* in_sizes, int n_in,
                              void* d_out, int out_size)
{
    const float* x     = (const float*)d_in[0];
    const float* pos   = (const float*)d_in[1];
    const float* w_qkv = (const float*)d_in[2];
    const float* b_qkv = (const float*)d_in[3];
    const float* w_out = (const float*)d_in[4];
    const float* b_out = (const float*)d_in[5];
    const float* w_ff1 = (const float*)d_in[6];
    const float* b_ff1 = (const float*)d_in[7];
    const float* w_ff2 = (const float*)d_in[8];
    const float* b_ff2 = (const float*)d_in[9];
    const float* w_rel = (const float*)d_in[10];
    const float* g1    = (const float*)d_in[11];
    const float* be1   = (const float*)d_in[12];
    const float* g2    = (const float*)d_in[13];
    const float* be2   = (const float*)d_in[14];
    float* out = (float*)d_out;

    float *qkv, *xt2, *y, *rel;
    __nv_bfloat16 *ah, *al, *gh, *gl;
    __nv_bfloat16 *wqh, *wql, *woh, *wol, *w1h, *w1l, *w2h, *w2l;
    cudaGetSymbolAddress((void**)&qkv, g_qkv);
    cudaGetSymbolAddress((void**)&xt2, g_xt2);
    cudaGetSymbolAddress((void**)&y,   g_y);
    cudaGetSymbolAddress((void**)&rel, g_rel);
    cudaGetSymbolAddress((void**)&ah,  g_act_h);
    cudaGetSymbolAddress((void**)&al,  g_act_l);
    cudaGetSymbolAddress((void**)&gh,  g_gel_h);
    cudaGetSymbolAddress((void**)&gl,  g_gel_l);
    cudaGetSymbolAddress((void**)&wqh, g_wqkv_h);
    cudaGetSymbolAddress((void**)&wql, g_wqkv_l);
    cudaGetSymbolAddress((void**)&woh, g_wout_h);
    cudaGetSymbolAddress((void**)&wol, g_wout_l);
    cudaGetSymbolAddress((void**)&w1h, g_wff1_h);
    cudaGetSymbolAddress((void**)&w1l, g_wff1_l);
    cudaGetSymbolAddress((void**)&w2h, g_wff2_h);
    cudaGetSymbolAddress((void**)&w2l, g_wff2_l);

    cudaFuncSetAttribute(gemm_tc<0>, cudaFuncAttributeMaxDynamicSharedMemorySize, GEMM_SMEM);
    cudaFuncSetAttribute(gemm_tc<1>, cudaFuncAttributeMaxDynamicSharedMemorySize, GEMM_SMEM);
    cudaFuncSetAttribute(gemm_tc<2>, cudaFuncAttributeMaxDynamicSharedMemorySize, GEMM_SMEM);
    cudaFuncSetAttribute(gemm_tc<3>, cudaFuncAttributeMaxDynamicSharedMemorySize, GEMM_SMEM);

    // weight split+transpose
    wconv_kernel<<<(768*256+255)/256, 256>>>(w_qkv, wqh, wql, 256, 768);
    wconv_kernel<<<(256*256+255)/256, 256>>>(w_out, woh, wol, 256, 256);
    wconv_kernel<<<(512*256+255)/256, 256>>>(w_ff1, w1h, w1l, 256, 512);
    wconv_kernel<<<(256*512+255)/256, 256>>>(w_ff2, w2h, w2l, 512, 256);
    // relpos bias
    relpos_kernel<<<B_*P_, 64>>>(pos, w_rel, rel);
    // LN1 + transpose -> act hi/lo
    ln_kernel<<<N_/8, 256>>>(x, g1, be1, ah, al, nullptr, 1);
    // QKV projection
    gemm_tc<0><<<dim3(768/128, N_/128), 256, GEMM_SMEM>>>(ah, al, wqh, wql, b_qkv, qkv, nullptr, nullptr, nullptr, 256, 768);
    // attention -> act hi/lo (reuse)
    attn_kernel<<<B_*T_*H_, 128>>>(qkv, rel, ah, al);
    // out projection + transposed residual(x)
    gemm_tc<1><<<dim3(256/128, N_/128), 256, GEMM_SMEM>>>(ah, al, woh, wol, b_out, xt2, nullptr, nullptr, x, 256, 256);
    // LN2 -> y fp32 + act hi/lo
    ln_kernel<<<N_/8, 256>>>(xt2, g2, be2, ah, al, y, 0);
    // FF1 + GELU -> gel hi/lo
    gemm_tc<2><<<dim3(512/128, N_/128), 256, GEMM_SMEM>>>(ah, al, w1h, w1l, b_ff1, nullptr, gh, gl, nullptr, 256, 512);
    // FF2 + residual(y) -> transposed store into d_out
    gemm_tc<3><<<dim3(256/128, N_/128), 256, GEMM_SMEM>>>(gh, gl, w2h, w2l, b_ff2, out, nullptr, nullptr, y, 512, 256);
}

// round 8
// speedup vs baseline: 1.7216x; 1.0120x over previous
#include <cuda_runtime.h>
#include <cuda_fp16.h>
#include <cstdint>
#include <math.h>

#define B_  8
#define P_  64
#define T_  512
#define D_  256
#define H_  8
#define FF_ 512
#define N_  (B_*T_*P_)   // 262144 rows

// ---------------- scratch (static device globals; no allocations) ----------
__device__ __half g_big[201326592];   // qkv (N*768) then FF1-out gel (N*512)
__device__ __half g_act[67108864];    // N*256 fp16 activations (LN out / attn out / LN2 out)
__device__ float  g_xt2[67108864];    // N*256 fp32 residual-1
__device__ float  g_y  [67108864];    // N*256 fp32 LN2 out
__device__ float  g_rel[262144];      // B*H*P*P
__device__ __half g_wqkv[196608];     // [768,256]
__device__ __half g_wout[65536];      // [256,256]
__device__ __half g_wff1[131072];     // [512,256]
__device__ __half g_wff2[131072];     // [256,512]

// ---------------- helpers ----------------------------------------------
__device__ __forceinline__ uint32_t smem_u32(const void* p) {
    uint32_t a;
    asm("{ .reg .u64 t; cvta.to.shared.u64 t, %1; cvt.u32.u64 %0, t; }" : "=r"(a) : "l"(p));
    return a;
}
#define SW128(o) ((o) ^ (((o) >> 3) & 0x70))

__device__ __forceinline__ void cpasync16(uint32_t s, const void* g) {
    asm volatile("cp.async.cg.shared.global [%0], [%1], 16;" :: "r"(s), "l"(g));
}
#define CP_COMMIT() asm volatile("cp.async.commit_group;" ::: "memory")
#define CP_WAIT(n)  asm volatile("cp.async.wait_group %0;" :: "n"(n) : "memory")

__device__ __forceinline__ void ldsm4(uint32_t* r, uint32_t addr) {
    asm volatile("ldmatrix.sync.aligned.m8n8.x4.shared.b16 {%0,%1,%2,%3}, [%4];"
        : "=r"(r[0]), "=r"(r[1]), "=r"(r[2]), "=r"(r[3]) : "r"(addr));
}
__device__ __forceinline__ void mma16816(float* d, const uint32_t* a, const uint32_t* b) {
    asm volatile("mma.sync.aligned.m16n8k16.row.col.f32.f16.f16.f32 "
        "{%0,%1,%2,%3}, {%4,%5,%6,%7}, {%8,%9}, {%0,%1,%2,%3};"
        : "+f"(d[0]), "+f"(d[1]), "+f"(d[2]), "+f"(d[3])
        : "r"(a[0]), "r"(a[1]), "r"(a[2]), "r"(a[3]), "r"(b[0]), "r"(b[1]));
}

__device__ __forceinline__ uint32_t pack_h2(float a, float b) {
    __half2 h = __floats2half2_rn(a, b);
    return *(uint32_t*)&h;
}
__device__ __forceinline__ void store_h4(__half* p, float4 v) {
    uint2 u; u.x = pack_h2(v.x, v.y); u.y = pack_h2(v.z, v.w);
    *(uint2*)p = u;
}

// ---------------- weight convert+transpose: [K,M] f32 -> [M,K] fp16 ---------
__global__ void wconv_kernel(const float* __restrict__ w,
                             __half* __restrict__ t, int K, int M)
{
    int idx = blockIdx.x * 256 + threadIdx.x;
    if (idx >= M * K) return;
    int m = idx / K, k = idx - m * K;
    t[idx] = __float2half(w[(long)k * M + m]);
}

// ---------------- relpos: (B,P,2) -> rel_h (B,H,P,P) ------------------------
__global__ void relpos_kernel(const float* __restrict__ pos,
                              const float* __restrict__ w_rel,
                              float* __restrict__ rel)
{
    int bp = blockIdx.x;
    int b = bp >> 6, p = bp & 63;
    int q = threadIdx.x;
    const float DEG = 0.017453292519943295f;
    float latp = pos[(b*64+p)*2]   * DEG;
    float lonp = pos[(b*64+p)*2+1] * DEG;
    float latq = pos[(b*64+q)*2]   * DEG;
    float lonq = pos[(b*64+q)*2+1] * DEG;
    float dlat = latp - latq, dlon = lonp - lonq;
    float dx = dlon * cosf((latp + latq) * 0.5f);
    float dy = dlat;
    float sdl = sinf(dlat*0.5f), sdo = sinf(dlon*0.5f);
    float a = sdl*sdl + cosf(latp)*cosf(latq)*sdo*sdo;
    float sa = fminf(sqrtf(fmaxf(a, 1e-12f)), 1.0f - 1e-7f);
    float dist = 2.0f * 6371.0f * asinf(sa) * (1.0f/500.0f);
    float bearing = atan2f(sinf(dlon)*cosf(latq),
                           cosf(latp)*sinf(latq) - sinf(latp)*cosf(latq)*cosf(dlon));
    float sb = sinf(bearing);
    #pragma unroll
    for (int h = 0; h < 8; h++) {
        float v = dx*w_rel[h] + dy*w_rel[8+h] + dist*w_rel[16+h] + sb*w_rel[24+h];
        rel[(((long)(b*8 + h))*64 + p)*64 + q] = v;
    }
}

// ---------------- LayerNorm -> fp16 (+ optional f32) ------------------------
__global__ void __launch_bounds__(256) ln_kernel(const float* __restrict__ in,
                          const float* __restrict__ g,
                          const float* __restrict__ be,
                          __half* __restrict__ oh,
                          float* __restrict__ of32, int transpose_in)
{
    int warp = threadIdx.x >> 5, lane = threadIdx.x & 31;
    long r = (long)blockIdx.x * 8 + warp;
    long src;
    if (transpose_in) {
        int b = (int)(r >> 15), t = (int)(r >> 6) & (T_-1), p = (int)r & (P_-1);
        src = (((long)(b*P_ + p))*T_ + t) * D_;
    } else {
        src = r * D_;
    }
    const float4* in4 = (const float4*)(in + src);
    float4 v0 = in4[lane];
    float4 v1 = in4[lane + 32];
    float s  = v0.x+v0.y+v0.z+v0.w + v1.x+v1.y+v1.z+v1.w;
    float sq = v0.x*v0.x+v0.y*v0.y+v0.z*v0.z+v0.w*v0.w
             + v1.x*v1.x+v1.y*v1.y+v1.z*v1.z+v1.w*v1.w;
    #pragma unroll
    for (int o = 16; o; o >>= 1) {
        s  += __shfl_xor_sync(0xffffffffu, s,  o);
        sq += __shfl_xor_sync(0xffffffffu, sq, o);
    }
    float mean = s * (1.0f/256.0f);
    float var  = sq * (1.0f/256.0f) - mean*mean;
    float rstd = rsqrtf(var + 1e-5f);
    const float4* g4  = (const float4*)g;
    const float4* be4 = (const float4*)be;
    float4 ga = g4[lane],  gb = g4[lane+32];
    float4 ba = be4[lane], bb = be4[lane+32];
    float4 o0, o1;
    o0.x = (v0.x-mean)*rstd*ga.x + ba.x;  o0.y = (v0.y-mean)*rstd*ga.y + ba.y;
    o0.z = (v0.z-mean)*rstd*ga.z + ba.z;  o0.w = (v0.w-mean)*rstd*ga.w + ba.w;
    o1.x = (v1.x-mean)*rstd*gb.x + bb.x;  o1.y = (v1.y-mean)*rstd*gb.y + bb.y;
    o1.z = (v1.z-mean)*rstd*gb.z + bb.z;  o1.w = (v1.w-mean)*rstd*gb.w + bb.w;
    store_h4(oh + r*D_ + lane*4,       o0);
    store_h4(oh + r*D_ + 128 + lane*4, o1);
    if (of32) {
        float4* o4 = (float4*)(of32 + r * D_);
        o4[lane]      = o0;
        o4[lane + 32] = o1;
    }
}

// ---------------- attention: one block per (b,t,h); fp16 in/out, fp32 math --
__global__ void __launch_bounds__(128) attn_kernel(const __half* __restrict__ qkv,
                            const float* __restrict__ rel,
                            __half* __restrict__ oh)
{
    int blk = blockIdx.x;
    int h = blk & 7;
    int bt = blk >> 3;
    int t = bt & (T_-1);
    int b = bt >> 9;

    __shared__ float qs[64][36];
    __shared__ float ks[64][36];
    __shared__ float vs[64][36];
    __shared__ float ss[64][65];

    const __half* base = qkv + ((long)(b*T_ + t)) * P_ * 768;
    int tid = threadIdx.x;
    for (int i = tid; i < 64*8; i += 128) {
        int p = i >> 3, d4 = (i & 7) * 4;
        uint2 uq = *(const uint2*)(base + p*768 +        h*32 + d4);
        uint2 uk = *(const uint2*)(base + p*768 + 256  + h*32 + d4);
        uint2 uv = *(const uint2*)(base + p*768 + 512  + h*32 + d4);
        __half2* hq = (__half2*)&uq; __half2* hk = (__half2*)&uk; __half2* hv = (__half2*)&uv;
        float2 a0 = __half22float2(hq[0]), a1 = __half22float2(hq[1]);
        qs[p][d4+0]=a0.x; qs[p][d4+1]=a0.y; qs[p][d4+2]=a1.x; qs[p][d4+3]=a1.y;
        float2 b0 = __half22float2(hk[0]), b1 = __half22float2(hk[1]);
        ks[p][d4+0]=b0.x; ks[p][d4+1]=b0.y; ks[p][d4+2]=b1.x; ks[p][d4+3]=b1.y;
        float2 c0 = __half22float2(hv[0]), c1 = __half22float2(hv[1]);
        vs[p][d4+0]=c0.x; vs[p][d4+1]=c0.y; vs[p][d4+2]=c1.x; vs[p][d4+3]=c1.y;
    }
    __syncthreads();

    const float scale = 0.17677669529663687f;
    const float* relb = rel + ((long)(b*8 + h)) * 64 * 64;

    int p  = tid >> 1;
    int q0 = (tid & 1) * 32;

    float qreg[32];
    #pragma unroll
    for (int j = 0; j < 8; j++) {
        float4 t4 = *(const float4*)&qs[p][j*4];
        qreg[j*4+0]=t4.x; qreg[j*4+1]=t4.y; qreg[j*4+2]=t4.z; qreg[j*4+3]=t4.w;
    }
    for (int qq = q0; qq < q0 + 32; qq++) {
        float s = 0.0f;
        #pragma unroll
        for (int j = 0; j < 8; j++) {
            float4 k4 = *(const float4*)&ks[qq][j*4];
            s += qreg[j*4+0]*k4.x + qreg[j*4+1]*k4.y + qreg[j*4+2]*k4.z + qreg[j*4+3]*k4.w;
        }
        ss[p][qq] = s * scale + relb[p*64 + qq];
    }
    __syncthreads();

    {
        int row = tid >> 1, half = tid & 1;
        float m = -1e30f;
        #pragma unroll
        for (int i = 0; i < 32; i++) m = fmaxf(m, ss[row][half*32 + i]);
        m = fmaxf(m, __shfl_xor_sync(0xffffffffu, m, 1));
        float sum = 0.0f;
        #pragma unroll
        for (int i = 0; i < 32; i++) {
            float e = __expf(ss[row][half*32 + i] - m);
            ss[row][half*32 + i] = e;
            sum += e;
        }
        sum += __shfl_xor_sync(0xffffffffu, sum, 1);
        float inv = 1.0f / sum;
        #pragma unroll
        for (int i = 0; i < 32; i++) ss[row][half*32 + i] *= inv;
    }
    __syncthreads();

    int d0 = (tid & 1) * 16;
    float acc[16];
    #pragma unroll
    for (int i = 0; i < 16; i++) acc[i] = 0.0f;
    for (int qq = 0; qq < 64; qq++) {
        float sv = ss[p][qq];
        #pragma unroll
        for (int j = 0; j < 4; j++) {
            float4 v4 = *(const float4*)&vs[qq][d0 + j*4];
            acc[j*4+0] += sv*v4.x; acc[j*4+1] += sv*v4.y;
            acc[j*4+2] += sv*v4.z; acc[j*4+3] += sv*v4.w;
        }
    }
    long ob = ((long)(b*T_ + t)) * P_ * 256 + p*256 + h*32 + d0;
    #pragma unroll
    for (int j = 0; j < 4; j++) {
        float4 v; v.x=acc[j*4+0]; v.y=acc[j*4+1]; v.z=acc[j*4+2]; v.w=acc[j*4+3];
        store_h4(oh + ob + j*4, v);
    }
}

// ---------------- HMMA fp16 GEMM, 128x128 tile, fused epilogues -------------
// MODE 0: Ch = fp16(A@W + bias)                (QKV, Mout=768)
// MODE 1: Cf = A@W + bias + x_transposed(aux)  (out-proj, Mout=256)
// MODE 2: Ch = fp16(gelu(A@W + bias))          (FF1, Mout=512)
// MODE 3: Cf[transposed] = A@W + bias + aux    (FF2, Mout=256)
// SMEM per buffer: A 16K | W 16K  (K-chunk 64, SW128), double buffered
#define GEMM_SMEM (2 * 32768)

template<int MODE>
__global__ void __launch_bounds__(256) gemm_tc(
    const __half* __restrict__ A,
    const __half* __restrict__ W,
    const float* __restrict__ bias,
    float* __restrict__ Cf,
    __half* __restrict__ Ch,
    const float* __restrict__ aux,
    int K, int Mout)
{
    extern __shared__ char smem[];
    uint32_t sb = smem_u32(smem);
    int tid = threadIdx.x, wid = tid >> 5, lane = tid & 31;
    long r0 = (long)blockIdx.y * 128;
    int  c0 = blockIdx.x * 128;
    int wm = wid & 3, wn = wid >> 2;

    int NC = K >> 6;

    // ---- prefetch chunk 0 ----
    // Each tile (A and W) is 128 rows x 8 x 16B segments = 1024 cp.asyncs.
    {
        #pragma unroll
        for (int it = 0; it < 4; it++) {
            int i = tid + it*256;
            int row = i >> 3, kq = i & 7;
            uint32_t sw = SW128((uint32_t)(row*128 + kq*16));
            cpasync16(sb + sw,         A + (r0+row)*(long)K + kq*8);
            cpasync16(sb + 16384 + sw, W + (long)(c0+row)*K + kq*8);
        }
        CP_COMMIT();
    }

    float acc[2][8][4];
    #pragma unroll
    for (int mt = 0; mt < 2; mt++)
        #pragma unroll
        for (int nt = 0; nt < 8; nt++)
            #pragma unroll
            for (int i = 0; i < 4; i++) acc[mt][nt][i] = 0.0f;

    for (int c = 0; c < NC; c++) {
        if (c + 1 < NC) {
            uint32_t base = sb + ((c+1) & 1) * 32768u;
            int kt = (c+1) << 6;
            #pragma unroll
            for (int it = 0; it < 4; it++) {
                int i = tid + it*256;
                int row = i >> 3, kq = i & 7;
                uint32_t sw = SW128((uint32_t)(row*128 + kq*16));
                cpasync16(base + sw,         A + (r0+row)*(long)K + kt + kq*8);
                cpasync16(base + 16384 + sw, W + (long)(c0+row)*K + kt + kq*8);
            }
            CP_COMMIT();
            CP_WAIT(1);
        } else {
            CP_WAIT(0);
        }
        __syncthreads();

        uint32_t base = sb + (c & 1) * 32768u;
        #pragma unroll
        for (int k16 = 0; k16 < 4; k16++) {
            uint32_t ah[2][4], bh[8][2];
            #pragma unroll
            for (int mt = 0; mt < 2; mt++) {
                int arow = wm*32 + mt*16 + (lane & 15);
                uint32_t kb = k16*32 + ((lane >> 4) << 4);
                uint32_t off = SW128((uint32_t)(arow*128) + kb);
                ldsm4(ah[mt], base + off);
            }
            #pragma unroll
            for (int np = 0; np < 4; np++) {
                int brow = wn*64 + np*16 + (lane & 7) + ((lane >> 4) & 1) * 8;
                uint32_t kb = k16*32 + ((lane >> 3) & 1) * 16;
                uint32_t off = SW128((uint32_t)(brow*128) + kb);
                ldsm4(&bh[np*2][0], base + 16384 + off);
            }
            #pragma unroll
            for (int mt = 0; mt < 2; mt++)
                #pragma unroll
                for (int nt = 0; nt < 8; nt++)
                    mma16816(acc[mt][nt], ah[mt], bh[nt]);
        }
        __syncthreads();
    }

    // ---- epilogue ----
    int rowb = wm*32 + (lane >> 2);
    int colb = c0 + wn*64 + (lane & 3) * 2;
    #pragma unroll
    for (int mt = 0; mt < 2; mt++) {
        #pragma unroll
        for (int half = 0; half < 2; half++) {
            long row = r0 + rowb + mt*16 + half*8;
            long trow = 0;
            if (MODE == 1 || MODE == 3) {
                int b = (int)(row >> 15), t = (int)(row >> 6) & (T_-1), p = (int)row & (P_-1);
                trow = (((long)(b*P_ + p))*T_ + t) * D_;
            }
            #pragma unroll
            for (int nt = 0; nt < 8; nt++) {
                int col = colb + nt*8;
                float2 v;
                v.x = acc[mt][nt][half*2+0];
                v.y = acc[mt][nt][half*2+1];
                float2 bb = *(const float2*)(bias + col);
                v.x += bb.x; v.y += bb.y;
                if (MODE == 0) {
                    *(uint32_t*)(Ch + row*(long)Mout + col) = pack_h2(v.x, v.y);
                } else if (MODE == 1) {
                    float2 xr = *(const float2*)(aux + trow + col);
                    v.x += xr.x; v.y += xr.y;
                    *(float2*)(Cf + row*(long)D_ + col) = v;
                } else if (MODE == 2) {
                    v.x = v.x * normcdff(v.x);
                    v.y = v.y * normcdff(v.y);
                    *(uint32_t*)(Ch + row*(long)Mout + col) = pack_h2(v.x, v.y);
                } else {
                    float2 yr = *(const float2*)(aux + row*(long)D_ + col);
                    v.x += yr.x; v.y += yr.y;
                    *(float2*)(Cf + trow + col) = v;
                }
            }
        }
    }
}

// ---------------- launch -----------------------------------------------------
extern "C" void kernel_launch(void* const* d_in, const int* in_sizes, int n_in,
                              void* d_out, int out_size)
{
    const float* x     = (const float*)d_in[0];
    const float* pos   = (const float*)d_in[1];
    const float* w_qkv = (const float*)d_in[2];
    const float* b_qkv = (const float*)d_in[3];
    const float* w_out = (const float*)d_in[4];
    const float* b_out = (const float*)d_in[5];
    const float* w_ff1 = (const float*)d_in[6];
    const float* b_ff1 = (const float*)d_in[7];
    const float* w_ff2 = (const float*)d_in[8];
    const float* b_ff2 = (const float*)d_in[9];
    const float* w_rel = (const float*)d_in[10];
    const float* g1    = (const float*)d_in[11];
    const float* be1   = (const float*)d_in[12];
    const float* g2    = (const float*)d_in[13];
    const float* be2   = (const float*)d_in[14];
    float* out = (float*)d_out;

    float *xt2, *y, *rel;
    __half *big, *act, *wq, *wo, *w1, *w2;
    cudaGetSymbolAddress((void**)&big, g_big);
    cudaGetSymbolAddress((void**)&act, g_act);
    cudaGetSymbolAddress((void**)&xt2, g_xt2);
    cudaGetSymbolAddress((void**)&y,   g_y);
    cudaGetSymbolAddress((void**)&rel, g_rel);
    cudaGetSymbolAddress((void**)&wq,  g_wqkv);
    cudaGetSymbolAddress((void**)&wo,  g_wout);
    cudaGetSymbolAddress((void**)&w1,  g_wff1);
    cudaGetSymbolAddress((void**)&w2,  g_wff2);

    cudaFuncSetAttribute(gemm_tc<0>, cudaFuncAttributeMaxDynamicSharedMemorySize, GEMM_SMEM);
    cudaFuncSetAttribute(gemm_tc<1>, cudaFuncAttributeMaxDynamicSharedMemorySize, GEMM_SMEM);
    cudaFuncSetAttribute(gemm_tc<2>, cudaFuncAttributeMaxDynamicSharedMemorySize, GEMM_SMEM);
    cudaFuncSetAttribute(gemm_tc<3>, cudaFuncAttributeMaxDynamicSharedMemorySize, GEMM_SMEM);

    // weight convert+transpose
    wconv_kernel<<<(768*256+255)/256, 256>>>(w_qkv, wq, 256, 768);
    wconv_kernel<<<(256*256+255)/256, 256>>>(w_out, wo, 256, 256);
    wconv_kernel<<<(512*256+255)/256, 256>>>(w_ff1, w1, 256, 512);
    wconv_kernel<<<(256*512+255)/256, 256>>>(w_ff2, w2, 512, 256);
    // relpos bias
    relpos_kernel<<<B_*P_, 64>>>(pos, w_rel, rel);
    // LN1 + transpose -> act fp16
    ln_kernel<<<N_/8, 256>>>(x, g1, be1, act, nullptr, 1);
    // QKV projection -> big (fp16)
    gemm_tc<0><<<dim3(768/128, N_/128), 256, GEMM_SMEM>>>(act, wq, b_qkv, nullptr, big, nullptr, 256, 768);
    // attention -> act fp16 (reuse)
    attn_kernel<<<B_*T_*H_, 128>>>(big, rel, act);
    // out projection + transposed residual(x) -> xt2 fp32
    gemm_tc<1><<<dim3(256/128, N_/128), 256, GEMM_SMEM>>>(act, wo, b_out, xt2, nullptr, x, 256, 256);
    // LN2 -> act fp16 + y fp32
    ln_kernel<<<N_/8, 256>>>(xt2, g2, be2, act, y, 0);
    // FF1 + GELU -> big (fp16, reuse)
    gemm_tc<2><<<dim3(512/128, N_/128), 256, GEMM_SMEM>>>(act, w1, b_ff1, nullptr, big, nullptr, 256, 512);
    // FF2 + residual(y) -> transposed store into d_out
    gemm_tc<3><<<dim3(256/128, N_/128), 256, GEMM_SMEM>>>(big, w2, b_ff2, out, nullptr, y, 512, 256);
}